// round 6
// baseline (speedup 1.0000x reference)
#include <cuda_runtime.h>
#include <math.h>

#define BB 4
#define TT 64
#define FF 64
#define UU 64
#define MM 64
#define TF 4096   // T*F

// Scratch (device globals: no allocation allowed)
__device__ float g_h[BB * TT * UU];
__device__ float g_out[BB * TT * FF];
__device__ float g_score[BB * TT * FF];
__device__ float g_flat[BB * TF];
__device__ float g_logit[BB * MM];
__device__ int   g_cnt1[BB];    // zero-init; reset by elected blocks each launch
__device__ int   g_cnt2[BB];
__device__ int   g_ready[BB];

// ---------------------------------------------------------------------------
// Single persistent kernel. Grid = 256 blocks (one per (b,t)), 64 threads.
// Phase A: h / output / score  (per-(b,t))
// Phase B: last block per batch -> argmax paths, extremes, flat (elected)
// Phase C: all blocks spin on ready flag, block (b,t) computes logit m=t
// Phase D: last block per batch -> softmax, targets, importance, dist
// All blocks are guaranteed resident (256 blocks x 2 warps, ~19KB smem).
// ---------------------------------------------------------------------------
__global__ void __launch_bounds__(64) fused(
    const float* __restrict__ inputs, const float* __restrict__ Wk,
    const float* __restrict__ bk,     const float* __restrict__ Wv,
    const float* __restrict__ bv,     const float* __restrict__ ws,
    const float* __restrict__ mem_keys, const float* __restrict__ mem_vals,
    float* __restrict__ d_dist, float* __restrict__ d_imp,
    float* __restrict__ out_final)
{
    int bt  = blockIdx.x;
    int b   = bt >> 6;
    int t   = bt & 63;
    int tid = threadIdx.x;     // 0..63
    int wid = tid >> 5, lane = tid & 31;

    __shared__ float s_score[TF];          // 16 KB (elected phase B)
    __shared__ float s_in[FF], s_h[UU];
    __shared__ int   s_idxt[TT], s_idxf[FF];
    __shared__ int   s_usel[UU], s_ssel[TT];
    __shared__ float s_hmax[TT], s_hmin[TT];
    __shared__ float s_q[2];
    __shared__ float s_part[2];
    __shared__ float s_attn[MM], s_tgt[FF];
    __shared__ float s_red[4];
    __shared__ int   s_flag;

    // ---------------- Phase A: kA work for this (b,t) ----------------
    s_in[tid] = inputs[bt * FF + tid];
    __syncthreads();

    float acc = bk[tid];
#pragma unroll 16
    for (int f = 0; f < FF; f++)
        acc = fmaf(s_in[f], Wk[f * UU + tid], acc);
    float hv = tanhf(acc);
    s_h[tid] = hv;
    g_h[bt * UU + tid] = hv;
    __syncthreads();

    float acc2 = bv[tid];
#pragma unroll 16
    for (int u = 0; u < UU; u++)
        acc2 = fmaf(s_h[u], Wv[u * FF + tid], acc2);
    g_out[bt * FF + tid]     = acc2;
    out_final[bt * FF + tid] = acc2;

    float c  = acc2 * ws[63];
    float sc = 0.f;
#pragma unroll 8
    for (int u = 0; u < UU; u++)
        sc += tanhf(s_h[u] * c);
    g_score[bt * FF + tid] = sc;

    // ---------------- Election 1 ----------------
    __threadfence();
    if (tid == 0) {
        int old = atomicAdd(&g_cnt1[b], 1);
        s_flag = (old == TT - 1);
    }
    __syncthreads();

    // ---------------- Phase B (elected): argmaxes, extremes, flat ------------
    if (s_flag) {
        if (tid == 0) atomicExch(&g_cnt1[b], 0);   // reset for next launch

        // Stage score matrix (L2-direct: other blocks wrote it)
        const float4* gs4 = (const float4*)(g_score + b * TF);
        float4* ss4 = (float4*)s_score;
        for (int i = tid; i < TF / 4; i += 64) ss4[i] = __ldcg(gs4 + i);
        s_usel[tid] = 0; s_ssel[tid] = 0;
        __syncthreads();

        // idx_f[f] = first argmax_t score[t,f]  (column scan, conflict-free)
        {
            int f = tid;
            float best = s_score[f]; int bi = 0;
            for (int tt2 = 1; tt2 < TT; tt2++) {
                float v = s_score[tt2 * FF + f];
                if (v > best) { best = v; bi = tt2; }
            }
            s_idxf[f] = bi;
        }
        // idx_t[t] = first argmax_f score[t,f]  (rotated scan to avoid 32-way
        // bank conflicts; explicit smallest-index tie-break preserves
        // first-occurrence semantics)
        {
            float best = -1e30f; int bi = FF;
            for (int k = 0; k < FF; k++) {
                int f = (tid + k) & 63;
                float v = s_score[tid * FF + f];
                if (v > best || (v == best && f < bi)) { best = v; bi = f; }
            }
            s_idxt[tid] = bi;
        }
        __syncthreads();

        s_usel[s_idxt[tid]] = 1;
        s_ssel[s_idxf[tid]] = 1;
        __syncthreads();

        if (tid == 0) {
            float qmax = -1e30f, qmin = 1e30f;
            for (int s = 0; s < TT; s++)
                if (s_ssel[s]) { float q = ws[s]; qmax = fmaxf(qmax, q); qmin = fminf(qmin, q); }
            s_q[0] = qmax; s_q[1] = qmin;
        }
        {
            const float* hr = g_h + (b * TT + tid) * UU;
            float hmax = -1e30f, hmin = 1e30f;
            for (int u = 0; u < UU; u++)
                if (s_usel[u]) { float h = __ldcg(hr + u); hmax = fmaxf(hmax, h); hmin = fminf(hmin, h); }
            s_hmax[tid] = hmax; s_hmin[tid] = hmin;
        }
        __syncthreads();

        // flat[i] = tanh(extremal h*q*x)  (max of tanh = tanh of max arg)
        {
            float qmax = s_q[0], qmin = s_q[1];
            for (int k = 0; k < TT; k++) {
                int i = k * FF + tid;
                float x  = __ldcg(g_out + b * TF + i);
                float hM = s_hmax[k], hm = s_hmin[k];
                float p1 = hM * qmax, p2 = hM * qmin, p3 = hm * qmax, p4 = hm * qmin;
                float pqmax = fmaxf(fmaxf(p1, p2), fmaxf(p3, p4));
                float pqmin = fminf(fminf(p1, p2), fminf(p3, p4));
                float arg = (x >= 0.f) ? x * pqmax : x * pqmin;
                g_flat[b * TF + i] = tanhf(arg);
            }
        }
        __threadfence();
        if (tid == 0) atomicExch(&g_ready[b], 1);   // release
    }

    // ---------------- Spin: wait for this batch's flat ----------------
    if (tid == 0) {
        while (atomicAdd(&g_ready[b], 0) == 0) __nanosleep(64);
    }
    __syncthreads();
    __threadfence();   // acquire before reading g_flat

    // ---------------- Phase C: logit m = t for this block ----------------
    {
        const float4* fl4 = (const float4*)(g_flat + b * TF);
        const float4* kr4 = (const float4*)(mem_keys + t * TF);
        float accd = 0.f;
#pragma unroll
        for (int j = 0; j < 16; j++) {
            int i = tid + j * 64;
            float4 a = __ldcg(fl4 + i);
            float4 k = __ldg(kr4 + i);
            accd = fmaf(a.x, k.x, accd);
            accd = fmaf(a.y, k.y, accd);
            accd = fmaf(a.z, k.z, accd);
            accd = fmaf(a.w, k.w, accd);
        }
        for (int o = 16; o; o >>= 1)
            accd += __shfl_xor_sync(0xffffffffu, accd, o);
        if (lane == 0) s_part[wid] = accd;
        __syncthreads();
        if (tid == 0) g_logit[b * MM + t] = s_part[0] + s_part[1];
    }

    // ---------------- Election 2 ----------------
    __threadfence();
    if (tid == 0) {
        int old = atomicAdd(&g_cnt2[b], 1);
        s_flag = (old == TT - 1);
    }
    __syncthreads();
    if (!s_flag) return;

    // ---------------- Phase D (elected): softmax/targets/importance/dist ----
    if (tid == 0) {
        atomicExch(&g_cnt2[b], 0);     // reset for next launch
        atomicExch(&g_ready[b], 0);
    }

    float v = __ldcg(g_logit + b * MM + tid);

    // max logit (two-warp shfl reduction)
    float m1 = v;
    for (int o = 16; o; o >>= 1) m1 = fmaxf(m1, __shfl_xor_sync(0xffffffffu, m1, o));
    if (lane == 0) s_red[wid] = m1;
    __syncthreads();
    float ml = fmaxf(s_red[0], s_red[1]);

    float e = expf(v - ml);
    s_attn[tid] = e;
    float s1 = e;
    for (int o = 16; o; o >>= 1) s1 += __shfl_xor_sync(0xffffffffu, s1, o);
    if (lane == 0) s_red[2 + wid] = s1;
    __syncthreads();
    float invsum = 1.f / (s_red[2] + s_red[3]);
    // importance = max(attn) = exp(ml - ml)/sum = invsum

    // targets[f] = (attn @ mem_vals) * invsum
    {
        float accv = 0.f;
#pragma unroll 8
        for (int m = 0; m < MM; m++)
            accv = fmaf(s_attn[m], __ldg(mem_vals + m * FF + tid), accv);
        s_tgt[tid] = accv * invsum;
    }
    __syncthreads();

    // dist[t] = 0.5 - hard_sigmoid(||inputs[b,t,:] - targets||); imp tiled
    {
        const float* ir = inputs + (b * TT + tid) * FF;
        float accn = 0.f;
#pragma unroll 8
        for (int f = 0; f < FF; f++) {
            float d = ir[f] - s_tgt[f];
            accn = fmaf(d, d, accn);
        }
        float nrm = sqrtf(accn);
        float hs  = fminf(fmaxf(0.2f * nrm + 0.5f, 0.f), 1.f);
        d_dist[b * TT + tid] = 0.5f - hs;
        d_imp [b * TT + tid] = invsum;
    }
}

// ---------------------------------------------------------------------------
// Output layout: dist [B*T] | importances [B*T] | output [B*T*F]
// ---------------------------------------------------------------------------
extern "C" void kernel_launch(void* const* d_in, const int* in_sizes, int n_in,
                              void* d_out, int out_size)
{
    const float* inputs   = (const float*)d_in[0];
    const float* Wk       = (const float*)d_in[1];
    const float* bk       = (const float*)d_in[2];
    const float* Wv       = (const float*)d_in[3];
    const float* bv       = (const float*)d_in[4];
    const float* ws       = (const float*)d_in[5];
    const float* mem_keys = (const float*)d_in[6];
    const float* mem_vals = (const float*)d_in[7];

    float* out       = (float*)d_out;
    float* d_dist    = out;                 // B*T
    float* d_imp     = out + BB * TT;       // B*T
    float* out_final = out + 2 * BB * TT;   // B*T*F

    fused<<<BB * TT, 64>>>(inputs, Wk, bk, Wv, bv, ws,
                           mem_keys, mem_vals, d_dist, d_imp, out_final);
}

// round 8
// speedup vs baseline: 1.4802x; 1.4802x over previous
#include <cuda_runtime.h>
#include <math.h>

#define BB 4
#define TT 64
#define FF 64
#define UU 64
#define MM 64
#define TF 4096   // T*F

// Scratch (device globals: no allocation allowed)
__device__ float g_h[BB * TT * UU];
__device__ float g_out[BB * TT * FF];
__device__ float g_score[BB * TT * FF];
__device__ float g_flat[BB * TF];
__device__ float g_logit[BB * MM];
__device__ int   g_cnt1[BB];    // zero-init; elected block resets each launch
__device__ int   g_cnt2[BB];

// ---------------------------------------------------------------------------
// K1: grid 256 (one block per (b,t)), 64 threads.
// Phase A: h / output / score for this (b,t).
// Election: the 64th-arriving block of each batch performs phase B
// (argmax paths, set extremes, flat) while all other blocks EXIT.
// No spinning anywhere.
// ---------------------------------------------------------------------------
__global__ void __launch_bounds__(64) k1(
    const float* __restrict__ inputs, const float* __restrict__ Wk,
    const float* __restrict__ bk,     const float* __restrict__ Wv,
    const float* __restrict__ bv,     const float* __restrict__ ws,
    float* __restrict__ out_final)
{
    int bt  = blockIdx.x;
    int b   = bt >> 6;
    int tid = threadIdx.x;     // 0..63

    __shared__ float s_in[FF], s_h[UU];
    __shared__ float s_score[TF];          // 16 KB (elected only)
    __shared__ int   s_idxt[TT], s_idxf[FF];
    __shared__ int   s_usel[UU], s_ssel[TT];
    __shared__ float s_hmax[TT], s_hmin[TT];
    __shared__ float s_q[2];
    __shared__ int   s_flag;

    // ---------------- Phase A ----------------
    s_in[tid] = inputs[bt * FF + tid];
    __syncthreads();

    float acc = bk[tid];
#pragma unroll 16
    for (int f = 0; f < FF; f++)
        acc = fmaf(s_in[f], Wk[f * UU + tid], acc);
    float hv = tanhf(acc);
    s_h[tid] = hv;
    g_h[bt * UU + tid] = hv;
    __syncthreads();

    float acc2 = bv[tid];
#pragma unroll 16
    for (int u = 0; u < UU; u++)
        acc2 = fmaf(s_h[u], Wv[u * FF + tid], acc2);
    g_out[bt * FF + tid]     = acc2;
    out_final[bt * FF + tid] = acc2;

    float c  = acc2 * ws[63];
    float sc = 0.f;
#pragma unroll 8
    for (int u = 0; u < UU; u++)
        sc += tanhf(s_h[u] * c);
    g_score[bt * FF + tid] = sc;

    // ---------------- Election (losers exit) ----------------
    __threadfence();
    if (tid == 0) {
        int old = atomicAdd(&g_cnt1[b], 1);
        s_flag = (old == TT - 1);
    }
    __syncthreads();
    if (!s_flag) return;
    if (tid == 0) atomicExch(&g_cnt1[b], 0);   // reset for next replay

    // ---------------- Phase B (elected block only) ----------------
    // Stage score matrix (written by sibling blocks -> L2)
    {
        const float4* gs4 = (const float4*)(g_score + b * TF);
        float4* ss4 = (float4*)s_score;
#pragma unroll 4
        for (int i = tid; i < TF / 4; i += 64) ss4[i] = __ldcg(gs4 + i);
    }
    s_usel[tid] = 0; s_ssel[tid] = 0;
    __syncthreads();

    // idx_f[f] = first argmax_t score[t,f]  (column scan, conflict-free)
    {
        int f = tid;
        float best = s_score[f]; int bi = 0;
        for (int t2 = 1; t2 < TT; t2++) {
            float v = s_score[t2 * FF + f];
            if (v > best) { best = v; bi = t2; }
        }
        s_idxf[f] = bi;
    }
    // idx_t[t] = first argmax_f score[t,f]  (rotated scan; explicit
    // smallest-index tie-break preserves first-occurrence semantics)
    {
        float best = -1e30f; int bi = FF;
        for (int k = 0; k < FF; k++) {
            int f = (tid + k) & 63;
            float v = s_score[tid * FF + f];
            if (v > best || (v == best && f < bi)) { best = v; bi = f; }
        }
        s_idxt[tid] = bi;
    }
    __syncthreads();

    s_usel[s_idxt[tid]] = 1;
    s_ssel[s_idxf[tid]] = 1;
    __syncthreads();

    if (tid == 0) {
        float qmax = -1e30f, qmin = 1e30f;
        for (int s = 0; s < TT; s++)
            if (s_ssel[s]) { float q = ws[s]; qmax = fmaxf(qmax, q); qmin = fminf(qmin, q); }
        s_q[0] = qmax; s_q[1] = qmin;
    }
    {
        const float* hr = g_h + (b * TT + tid) * UU;
        float hmax = -1e30f, hmin = 1e30f;
        for (int u = 0; u < UU; u++)
            if (s_usel[u]) { float h = __ldcg(hr + u); hmax = fmaxf(hmax, h); hmin = fminf(hmin, h); }
        s_hmax[tid] = hmax; s_hmin[tid] = hmin;
    }
    __syncthreads();

    // flat[i] = tanh(extremal h*q*x), vectorized: each float4 lies in one row
    {
        float qmax = s_q[0], qmin = s_q[1];
        const float4* go4 = (const float4*)(g_out + b * TF);
        float4*       gf4 = (float4*)(g_flat + b * TF);
#pragma unroll 4
        for (int i4 = tid; i4 < TF / 4; i4 += 64) {
            int t2 = i4 >> 4;                    // (4*i4)>>6
            float hM = s_hmax[t2], hm = s_hmin[t2];
            float p1 = hM * qmax, p2 = hM * qmin, p3 = hm * qmax, p4 = hm * qmin;
            float pqmax = fmaxf(fmaxf(p1, p2), fmaxf(p3, p4));
            float pqmin = fminf(fminf(p1, p2), fminf(p3, p4));
            float4 x = __ldcg(go4 + i4);
            float4 r;
            r.x = tanhf((x.x >= 0.f) ? x.x * pqmax : x.x * pqmin);
            r.y = tanhf((x.y >= 0.f) ? x.y * pqmax : x.y * pqmin);
            r.z = tanhf((x.z >= 0.f) ? x.z * pqmax : x.z * pqmin);
            r.w = tanhf((x.w >= 0.f) ? x.w * pqmax : x.w * pqmin);
            gf4[i4] = r;
        }
    }
}

// ---------------------------------------------------------------------------
// K2: grid (MM, BB), 128 threads. Block (m,b): logit[b,m] = flat.mem_keys[m].
// Election: 64th-arriving block of each batch does softmax/targets/dist.
// ---------------------------------------------------------------------------
__global__ void __launch_bounds__(128) k2(
    const float* __restrict__ inputs, const float* __restrict__ mem_keys,
    const float* __restrict__ mem_vals,
    float* __restrict__ d_dist, float* __restrict__ d_imp)
{
    int m   = blockIdx.x;     // 0..63
    int b   = blockIdx.y;     // 0..3
    int tid = threadIdx.x;    // 0..127
    int wid = tid >> 5, lane = tid & 31;

    __shared__ float s_part[4];
    __shared__ float s_attn[MM], s_tgt[FF];
    __shared__ float s_red[4];
    __shared__ int   s_flag;

    // ---------------- logits GEMV ----------------
    {
        const float4* fl4 = (const float4*)(g_flat + b * TF);
        const float4* kr4 = (const float4*)(mem_keys + m * TF);
        float accd = 0.f;
#pragma unroll
        for (int j = 0; j < 8; j++) {
            int i = tid + j * 128;
            float4 a = __ldcg(fl4 + i);
            float4 k = __ldg(kr4 + i);
            accd = fmaf(a.x, k.x, accd);
            accd = fmaf(a.y, k.y, accd);
            accd = fmaf(a.z, k.z, accd);
            accd = fmaf(a.w, k.w, accd);
        }
        for (int o = 16; o; o >>= 1)
            accd += __shfl_xor_sync(0xffffffffu, accd, o);
        if (lane == 0) s_part[wid] = accd;
        __syncthreads();
        if (tid == 0)
            g_logit[b * MM + m] = s_part[0] + s_part[1] + s_part[2] + s_part[3];
    }

    // ---------------- Election (losers exit) ----------------
    __threadfence();
    if (tid == 0) {
        int old = atomicAdd(&g_cnt2[b], 1);
        s_flag = (old == MM - 1);
    }
    __syncthreads();
    if (!s_flag) return;
    if (tid == 0) atomicExch(&g_cnt2[b], 0);   // reset for next replay

    // ---------------- softmax / targets / importance / dist ----------------
    float v = (tid < MM) ? __ldcg(g_logit + b * MM + tid) : -1e30f;

    // max logit across the two active warps
    float m1 = v;
    for (int o = 16; o; o >>= 1) m1 = fmaxf(m1, __shfl_xor_sync(0xffffffffu, m1, o));
    if (lane == 0 && wid < 2) s_red[wid] = m1;
    __syncthreads();
    float ml = fmaxf(s_red[0], s_red[1]);

    float e = (tid < MM) ? expf(v - ml) : 0.f;
    if (tid < MM) s_attn[tid] = e;
    float s1 = e;
    for (int o = 16; o; o >>= 1) s1 += __shfl_xor_sync(0xffffffffu, s1, o);
    if (lane == 0 && wid < 2) s_red[2 + wid] = s1;
    __syncthreads();
    float invsum = 1.f / (s_red[2] + s_red[3]);
    // importance = max(attn) = exp(0)/sum = invsum

    // targets[f] = (attn @ mem_vals) * invsum
    if (tid < FF) {
        float accv = 0.f;
#pragma unroll 8
        for (int mm = 0; mm < MM; mm++)
            accv = fmaf(s_attn[mm], __ldg(mem_vals + mm * FF + tid), accv);
        s_tgt[tid] = accv * invsum;
    }
    __syncthreads();

    // dist[t] = 0.5 - hard_sigmoid(||inputs[b,t,:] - targets||); imp tiled
    if (tid < TT) {
        const float* ir = inputs + (b * TT + tid) * FF;
        float accn = 0.f;
#pragma unroll 8
        for (int f = 0; f < FF; f++) {
            float d = ir[f] - s_tgt[f];
            accn = fmaf(d, d, accn);
        }
        float nrm = sqrtf(accn);
        float hs  = fminf(fmaxf(0.2f * nrm + 0.5f, 0.f), 1.f);
        d_dist[b * TT + tid] = 0.5f - hs;
        d_imp [b * TT + tid] = invsum;
    }
}

// ---------------------------------------------------------------------------
// Output layout: dist [B*T] | importances [B*T] | output [B*T*F]
// ---------------------------------------------------------------------------
extern "C" void kernel_launch(void* const* d_in, const int* in_sizes, int n_in,
                              void* d_out, int out_size)
{
    const float* inputs   = (const float*)d_in[0];
    const float* Wk       = (const float*)d_in[1];
    const float* bk       = (const float*)d_in[2];
    const float* Wv       = (const float*)d_in[3];
    const float* bv       = (const float*)d_in[4];
    const float* ws       = (const float*)d_in[5];
    const float* mem_keys = (const float*)d_in[6];
    const float* mem_vals = (const float*)d_in[7];

    float* out       = (float*)d_out;
    float* d_dist    = out;                 // B*T
    float* d_imp     = out + BB * TT;       // B*T
    float* out_final = out + 2 * BB * TT;   // B*T*F

    k1<<<BB * TT, 64>>>(inputs, Wk, bk, Wv, bv, ws, out_final);
    dim3 g2(MM, BB);
    k2<<<g2, 128>>>(inputs, mem_keys, mem_vals, d_dist, d_imp);
}

// round 9
// speedup vs baseline: 2.0875x; 1.4103x over previous
#include <cuda_runtime.h>
#include <math.h>

#define BB 4
#define TT 64
#define FF 64
#define UU 64
#define MM 64
#define TF 4096   // T*F

// Scratch (device globals: no allocation allowed)
__device__ float  g_h[BB * TT * UU];
__device__ float  g_out[BB * TT * FF];
__device__ float  g_score[BB * TT * FF];
__device__ float2 g_pq[BB * TT];       // (pqmax, pqmin) per (b,t)
__device__ float  g_logit[BB * MM];
__device__ int    g_cnt1[BB];          // zero-init; elected resets each launch
__device__ int    g_cnt2[BB];

// ---------------------------------------------------------------------------
// K1: grid (16, BB), 256 threads. Block handles 4 timesteps of batch b.
// Phase A: h / output / score for 4 (b,t) rows.
// Election: 16th-arriving block per batch does phase B at 256-thread width:
// argmax paths, selected sets, extremes -> g_pq (tiny). Losers exit.
// ---------------------------------------------------------------------------
__global__ void __launch_bounds__(256) k1(
    const float* __restrict__ inputs, const float* __restrict__ Wk,
    const float* __restrict__ bk,     const float* __restrict__ Wv,
    const float* __restrict__ bv,     const float* __restrict__ ws,
    float* __restrict__ out_final)
{
    int b   = blockIdx.y;
    int tid = threadIdx.x;          // 0..255
    int lt  = tid >> 6;             // local t 0..3
    int f   = tid & 63;             // f / u index
    int t   = (blockIdx.x << 2) + lt;
    int bt  = b * TT + t;
    int wid = tid >> 5, lane = tid & 31;

    __shared__ float s_in[4][FF], s_h[4][FF];
    __shared__ float s_score[TF];           // 16 KB (elected only)
    __shared__ int   s_idxt[TT], s_idxf[FF];
    __shared__ int   s_usel[UU], s_ssel[TT];
    __shared__ float2 s_qred[8];
    __shared__ float s_q[2];
    __shared__ int   s_flag;

    // ---------------- Phase A ----------------
    s_in[lt][f] = inputs[bt * FF + f];
    __syncthreads();

    float acc = bk[f];
#pragma unroll 16
    for (int k = 0; k < FF; k++)
        acc = fmaf(s_in[lt][k], Wk[k * UU + f], acc);
    float hv = tanhf(acc);
    s_h[lt][f] = hv;
    g_h[bt * UU + f] = hv;
    __syncthreads();

    float acc2 = bv[f];
#pragma unroll 16
    for (int u = 0; u < UU; u++)
        acc2 = fmaf(s_h[lt][u], Wv[u * FF + f], acc2);
    g_out[bt * FF + f]     = acc2;
    out_final[bt * FF + f] = acc2;

    float c  = acc2 * __ldg(ws + 63);
    float sc = 0.f;
#pragma unroll 8
    for (int u = 0; u < UU; u++)
        sc += tanhf(s_h[lt][u] * c);
    g_score[bt * FF + f] = sc;

    // ---------------- Election (losers exit) ----------------
    __threadfence();
    if (tid == 0) {
        int old = atomicAdd(&g_cnt1[b], 1);
        s_flag = (old == 15);
    }
    __syncthreads();
    if (!s_flag) return;
    if (tid == 0) atomicExch(&g_cnt1[b], 0);   // reset for next replay

    // ---------------- Phase B (elected block, 256 threads) ----------------
    // Stage score matrix (siblings wrote it -> L2)
    {
        const float4* gs4 = (const float4*)(g_score + b * TF);
        float4* ss4 = (float4*)s_score;
        float4 r0 = __ldcg(gs4 + tid);
        float4 r1 = __ldcg(gs4 + tid + 256);
        float4 r2 = __ldcg(gs4 + tid + 512);
        float4 r3 = __ldcg(gs4 + tid + 768);
        ss4[tid]       = r0;
        ss4[tid + 256] = r1;
        ss4[tid + 512] = r2;
        ss4[tid + 768] = r3;
    }
    if (tid < 64) { s_usel[tid] = 0; s_ssel[tid] = 0; }
    __syncthreads();

    // idx_f[f] = first argmax_t (column scan, conflict-free) — threads 0..63
    // idx_t[t] = first argmax_f (rotated row scan + smallest-index tie-break)
    if (tid < 64) {
        int ff = tid;
        float best = s_score[ff]; int bi = 0;
#pragma unroll 8
        for (int t2 = 1; t2 < TT; t2++) {
            float v = s_score[t2 * FF + ff];
            if (v > best) { best = v; bi = t2; }
        }
        s_idxf[ff] = bi;
    } else if (tid < 128) {
        int tt2 = tid - 64;
        float best = -1e30f; int bi = FF;
#pragma unroll 8
        for (int k = 0; k < FF; k++) {
            int ff = (tt2 + k) & 63;
            float v = s_score[tt2 * FF + ff];
            if (v > best || (v == best && ff < bi)) { best = v; bi = ff; }
        }
        s_idxt[tt2] = bi;
    }
    __syncthreads();

    if (tid < 64) { s_usel[s_idxt[tid]] = 1; s_ssel[s_idxf[tid]] = 1; }
    __syncthreads();

    // q extremes over selected s — parallel shfl reduction across all warps
    {
        float w  = (tid < 64 && s_ssel[tid]) ? __ldg(ws + tid) : 0.f;
        bool  on = (tid < 64) && s_ssel[tid];
        float qmx = on ? w : -1e30f;
        float qmn = on ? w :  1e30f;
        for (int o = 16; o; o >>= 1) {
            qmx = fmaxf(qmx, __shfl_xor_sync(0xffffffffu, qmx, o));
            qmn = fminf(qmn, __shfl_xor_sync(0xffffffffu, qmn, o));
        }
        if (lane == 0) s_qred[wid] = make_float2(qmx, qmn);
    }
    __syncthreads();
    if (tid == 0) {
        float qmx = -1e30f, qmn = 1e30f;
#pragma unroll
        for (int w2 = 0; w2 < 8; w2++) {
            qmx = fmaxf(qmx, s_qred[w2].x);
            qmn = fminf(qmn, s_qred[w2].y);
        }
        s_q[0] = qmx; s_q[1] = qmn;
    }

    // h extremes per t over selected u (threads 0..63, one t each)
    float hmax = -1e30f, hmin = 1e30f;
    if (tid < 64) {
        const float* hr = g_h + (b * TT + tid) * UU;
#pragma unroll 8
        for (int u = 0; u < UU; u++) {
            float h = __ldcg(hr + u);
            if (s_usel[u]) { hmax = fmaxf(hmax, h); hmin = fminf(hmin, h); }
        }
    }
    __syncthreads();

    // pq per t -> global (tiny)
    if (tid < 64) {
        float qmax = s_q[0], qmin = s_q[1];
        float p1 = hmax * qmax, p2 = hmax * qmin, p3 = hmin * qmax, p4 = hmin * qmin;
        float pqmax = fmaxf(fmaxf(p1, p2), fmaxf(p3, p4));
        float pqmin = fminf(fminf(p1, p2), fminf(p3, p4));
        g_pq[b * TT + tid] = make_float2(pqmax, pqmin);
    }
}

// ---------------------------------------------------------------------------
// K2: grid (MM, BB), 128 threads. Block (m,b):
//   logit[b,m] = sum_i tanh(extremal(g_out[b,i])) * mem_keys[m,i]
// flat computed inline from g_out + g_pq (no g_flat round trip).
// Register-batched loads (MLP=16). Elected 64th block per batch does
// softmax / targets / importance / dist.
// ---------------------------------------------------------------------------
__global__ void __launch_bounds__(128) k2(
    const float* __restrict__ inputs, const float* __restrict__ mem_keys,
    const float* __restrict__ mem_vals,
    float* __restrict__ d_dist, float* __restrict__ d_imp)
{
    int m   = blockIdx.x;     // 0..63
    int b   = blockIdx.y;     // 0..3
    int tid = threadIdx.x;    // 0..127
    int wid = tid >> 5, lane = tid & 31;

    __shared__ float2 s_pq[TT];
    __shared__ float s_part[4];
    __shared__ float s_attn[MM];
    __shared__ float s_tgt2[2][FF];
    __shared__ float s_tgt[FF];
    __shared__ float s_red[4];
    __shared__ int   s_flag;

    if (tid < 64) s_pq[tid] = __ldcg(g_pq + b * TT + tid);

    // ---- batched loads: all 16 float4 in flight before any math ----
    const float4* go4 = (const float4*)(g_out + b * TF);
    const float4* kr4 = (const float4*)(mem_keys + m * TF);
    float4 a[8], kk[8];
#pragma unroll
    for (int j = 0; j < 8; j++) a[j]  = __ldcg(go4 + tid + j * 128);
#pragma unroll
    for (int j = 0; j < 8; j++) kk[j] = __ldg(kr4 + tid + j * 128);
    __syncthreads();   // s_pq ready

    float accd = 0.f;
#pragma unroll
    for (int j = 0; j < 8; j++) {
        int i4 = tid + j * 128;
        float2 pq = s_pq[i4 >> 4];
        float fx = tanhf((a[j].x >= 0.f) ? a[j].x * pq.x : a[j].x * pq.y);
        float fy = tanhf((a[j].y >= 0.f) ? a[j].y * pq.x : a[j].y * pq.y);
        float fz = tanhf((a[j].z >= 0.f) ? a[j].z * pq.x : a[j].z * pq.y);
        float fw = tanhf((a[j].w >= 0.f) ? a[j].w * pq.x : a[j].w * pq.y);
        accd = fmaf(fx, kk[j].x, accd);
        accd = fmaf(fy, kk[j].y, accd);
        accd = fmaf(fz, kk[j].z, accd);
        accd = fmaf(fw, kk[j].w, accd);
    }
    for (int o = 16; o; o >>= 1)
        accd += __shfl_xor_sync(0xffffffffu, accd, o);
    if (lane == 0) s_part[wid] = accd;
    __syncthreads();
    if (tid == 0)
        g_logit[b * MM + m] = s_part[0] + s_part[1] + s_part[2] + s_part[3];

    // ---------------- Election (losers exit) ----------------
    __threadfence();
    if (tid == 0) {
        int old = atomicAdd(&g_cnt2[b], 1);
        s_flag = (old == MM - 1);
    }
    __syncthreads();
    if (!s_flag) return;
    if (tid == 0) atomicExch(&g_cnt2[b], 0);   // reset for next replay

    // ---------------- softmax / targets / importance / dist ----------------
    float v = (tid < MM) ? __ldcg(g_logit + b * MM + tid) : -1e30f;

    float m1 = v;
    for (int o = 16; o; o >>= 1) m1 = fmaxf(m1, __shfl_xor_sync(0xffffffffu, m1, o));
    if (lane == 0 && wid < 2) s_red[wid] = m1;
    __syncthreads();
    float ml = fmaxf(s_red[0], s_red[1]);

    float e = (tid < MM) ? expf(v - ml) : 0.f;
    if (tid < MM) s_attn[tid] = e;
    float s1 = e;
    for (int o = 16; o; o >>= 1) s1 += __shfl_xor_sync(0xffffffffu, s1, o);
    if (lane == 0 && wid < 2) s_red[2 + wid] = s1;
    __syncthreads();
    float invsum = 1.f / (s_red[2] + s_red[3]);
    // importance = max(attn) = exp(0) * invsum = invsum

    // targets: 2-way split over m (threads 0-63: m 0..31, 64-127: m 32..63)
    {
        int f    = tid & 63;
        int half = tid >> 6;
        float accv = 0.f;
#pragma unroll 8
        for (int mm = 0; mm < 32; mm++) {
            int mr = half * 32 + mm;
            accv = fmaf(s_attn[mr], __ldg(mem_vals + mr * FF + f), accv);
        }
        s_tgt2[half][f] = accv;
    }
    __syncthreads();
    if (tid < FF) s_tgt[tid] = (s_tgt2[0][tid] + s_tgt2[1][tid]) * invsum;
    __syncthreads();

    // dist[t] = 0.5 - hard_sigmoid(||inputs[b,t,:] - targets||)
    if (tid < TT) {
        const float4* ir4 = (const float4*)(inputs + (b * TT + tid) * FF);
        const float4* tg4 = (const float4*)s_tgt;
        float4 xr[16];
#pragma unroll
        for (int j = 0; j < 16; j++) xr[j] = __ldg(ir4 + j);
        float accn = 0.f;
#pragma unroll
        for (int j = 0; j < 16; j++) {
            float4 tg = tg4[j];
            float dx = xr[j].x - tg.x, dy = xr[j].y - tg.y;
            float dz = xr[j].z - tg.z, dw = xr[j].w - tg.w;
            accn = fmaf(dx, dx, accn);
            accn = fmaf(dy, dy, accn);
            accn = fmaf(dz, dz, accn);
            accn = fmaf(dw, dw, accn);
        }
        float nrm = sqrtf(accn);
        float hs  = fminf(fmaxf(0.2f * nrm + 0.5f, 0.f), 1.f);
        d_dist[b * TT + tid] = 0.5f - hs;
        d_imp [b * TT + tid] = invsum;
    }
}

// ---------------------------------------------------------------------------
// Output layout: dist [B*T] | importances [B*T] | output [B*T*F]
// ---------------------------------------------------------------------------
extern "C" void kernel_launch(void* const* d_in, const int* in_sizes, int n_in,
                              void* d_out, int out_size)
{
    const float* inputs   = (const float*)d_in[0];
    const float* Wk       = (const float*)d_in[1];
    const float* bk       = (const float*)d_in[2];
    const float* Wv       = (const float*)d_in[3];
    const float* bv       = (const float*)d_in[4];
    const float* ws       = (const float*)d_in[5];
    const float* mem_keys = (const float*)d_in[6];
    const float* mem_vals = (const float*)d_in[7];

    float* out       = (float*)d_out;
    float* d_dist    = out;                 // B*T
    float* d_imp     = out + BB * TT;       // B*T
    float* out_final = out + 2 * BB * TT;   // B*T*F

    dim3 g1(16, BB);
    k1<<<g1, 256>>>(inputs, Wk, bk, Wv, bv, ws, out_final);
    dim3 g2(MM, BB);
    k2<<<g2, 128>>>(inputs, mem_keys, mem_vals, d_dist, d_imp);
}

// round 10
// speedup vs baseline: 2.1913x; 1.0497x over previous
#include <cuda_runtime.h>
#include <math.h>

#define BB 4
#define TT 64
#define FF 64
#define UU 64
#define MM 64
#define TF 4096   // T*F

// Scratch (device globals: no allocation allowed)
__device__ float  g_h[BB * TT * UU];
__device__ float  g_out[BB * TT * FF];
__device__ float  g_score[BB * TT * FF];
__device__ float2 g_pq[BB * TT];       // (pqmax, pqmin) per (b,t)
__device__ float  g_logit[BB * MM];
__device__ int    g_cnt1[BB];          // zero-init; elected resets each launch
__device__ int    g_cnt2[BB];

// Fast hardware tanh (sm_75+): ~2^-11 relative error. Used ONLY where the
// result feeds argmax comparisons (score) or a 4096-term averaged dot
// product (flat) — never for the directly-checked `output` tensor.
__device__ __forceinline__ float tanh_fast(float x) {
    float y;
    asm("tanh.approx.f32 %0, %1;" : "=f"(y) : "f"(x));
    return y;
}

// ---------------------------------------------------------------------------
// K1: grid (16, BB), 256 threads. Block handles 4 timesteps of batch b.
// Phase A: h / output / score for 4 (b,t) rows.
// Election: 16th-arriving block per batch does phase B at 256-thread width:
// argmax paths, selected sets, extremes -> g_pq (tiny). Losers exit.
// ---------------------------------------------------------------------------
__global__ void __launch_bounds__(256) k1(
    const float* __restrict__ inputs, const float* __restrict__ Wk,
    const float* __restrict__ bk,     const float* __restrict__ Wv,
    const float* __restrict__ bv,     const float* __restrict__ ws,
    float* __restrict__ out_final)
{
    int b   = blockIdx.y;
    int tid = threadIdx.x;          // 0..255
    int lt  = tid >> 6;             // local t 0..3
    int f   = tid & 63;             // f / u index
    int t   = (blockIdx.x << 2) + lt;
    int bt  = b * TT + t;
    int wid = tid >> 5, lane = tid & 31;

    __shared__ float s_in[4][FF], s_h[4][FF];
    __shared__ float s_score[TF];           // 16 KB (elected only)
    __shared__ int   s_idxt[TT], s_idxf[FF];
    __shared__ int   s_usel[UU], s_ssel[TT];
    __shared__ float2 s_qred[8];
    __shared__ float s_q[2];
    __shared__ int   s_flag;

    // ---------------- Phase A ----------------
    s_in[lt][f] = inputs[bt * FF + f];
    __syncthreads();

    float acc = bk[f];
#pragma unroll 16
    for (int k = 0; k < FF; k++)
        acc = fmaf(s_in[lt][k], Wk[k * UU + f], acc);
    float hv = tanhf(acc);          // accurate: h feeds checked `output`
    s_h[lt][f] = hv;
    g_h[bt * UU + f] = hv;
    __syncthreads();

    float acc2 = bv[f];
#pragma unroll 16
    for (int u = 0; u < UU; u++)
        acc2 = fmaf(s_h[lt][u], Wv[u * FF + f], acc2);
    g_out[bt * FF + f]     = acc2;
    out_final[bt * FF + f] = acc2;

    // score: feeds argmax only -> hardware tanh
    float c  = acc2 * __ldg(ws + 63);
    float sc = 0.f;
#pragma unroll 16
    for (int u = 0; u < UU; u++)
        sc += tanh_fast(s_h[lt][u] * c);
    g_score[bt * FF + f] = sc;

    // ---------------- Election (losers exit) ----------------
    __threadfence();
    if (tid == 0) {
        int old = atomicAdd(&g_cnt1[b], 1);
        s_flag = (old == 15);
    }
    __syncthreads();
    if (!s_flag) return;
    if (tid == 0) atomicExch(&g_cnt1[b], 0);   // reset for next replay

    // ---------------- Phase B (elected block, 256 threads) ----------------
    // Stage score matrix (siblings wrote it -> L2)
    {
        const float4* gs4 = (const float4*)(g_score + b * TF);
        float4* ss4 = (float4*)s_score;
        float4 r0 = __ldcg(gs4 + tid);
        float4 r1 = __ldcg(gs4 + tid + 256);
        float4 r2 = __ldcg(gs4 + tid + 512);
        float4 r3 = __ldcg(gs4 + tid + 768);
        ss4[tid]       = r0;
        ss4[tid + 256] = r1;
        ss4[tid + 512] = r2;
        ss4[tid + 768] = r3;
    }
    if (tid < 64) { s_usel[tid] = 0; s_ssel[tid] = 0; }
    __syncthreads();

    // idx_f[f] = first argmax_t (column scan, conflict-free) — threads 0..63
    // idx_t[t] = first argmax_f (rotated row scan + smallest-index tie-break)
    if (tid < 64) {
        int ff = tid;
        float best = s_score[ff]; int bi = 0;
#pragma unroll 8
        for (int t2 = 1; t2 < TT; t2++) {
            float v = s_score[t2 * FF + ff];
            if (v > best) { best = v; bi = t2; }
        }
        s_idxf[ff] = bi;
    } else if (tid < 128) {
        int tt2 = tid - 64;
        float best = -1e30f; int bi = FF;
#pragma unroll 8
        for (int k = 0; k < FF; k++) {
            int ff = (tt2 + k) & 63;
            float v = s_score[tt2 * FF + ff];
            if (v > best || (v == best && ff < bi)) { best = v; bi = ff; }
        }
        s_idxt[tt2] = bi;
    }
    __syncthreads();

    if (tid < 64) { s_usel[s_idxt[tid]] = 1; s_ssel[s_idxf[tid]] = 1; }
    __syncthreads();

    // q extremes over selected s — parallel shfl reduction across all warps
    {
        float w  = (tid < 64 && s_ssel[tid]) ? __ldg(ws + tid) : 0.f;
        bool  on = (tid < 64) && s_ssel[tid];
        float qmx = on ? w : -1e30f;
        float qmn = on ? w :  1e30f;
        for (int o = 16; o; o >>= 1) {
            qmx = fmaxf(qmx, __shfl_xor_sync(0xffffffffu, qmx, o));
            qmn = fminf(qmn, __shfl_xor_sync(0xffffffffu, qmn, o));
        }
        if (lane == 0) s_qred[wid] = make_float2(qmx, qmn);
    }
    __syncthreads();
    if (tid == 0) {
        float qmx = -1e30f, qmn = 1e30f;
#pragma unroll
        for (int w2 = 0; w2 < 8; w2++) {
            qmx = fmaxf(qmx, s_qred[w2].x);
            qmn = fminf(qmn, s_qred[w2].y);
        }
        s_q[0] = qmx; s_q[1] = qmn;
    }

    // h extremes per t over selected u (threads 0..63, one t each)
    float hmax = -1e30f, hmin = 1e30f;
    if (tid < 64) {
        const float* hr = g_h + (b * TT + tid) * UU;
#pragma unroll 8
        for (int u = 0; u < UU; u++) {
            float h = __ldcg(hr + u);
            if (s_usel[u]) { hmax = fmaxf(hmax, h); hmin = fminf(hmin, h); }
        }
    }
    __syncthreads();

    // pq per t -> global (tiny)
    if (tid < 64) {
        float qmax = s_q[0], qmin = s_q[1];
        float p1 = hmax * qmax, p2 = hmax * qmin, p3 = hmin * qmax, p4 = hmin * qmin;
        float pqmax = fmaxf(fmaxf(p1, p2), fmaxf(p3, p4));
        float pqmin = fminf(fminf(p1, p2), fminf(p3, p4));
        g_pq[b * TT + tid] = make_float2(pqmax, pqmin);
    }
}

// ---------------------------------------------------------------------------
// K2: grid (MM, BB), 128 threads. Block (m,b):
//   logit[b,m] = sum_i tanh(extremal(g_out[b,i])) * mem_keys[m,i]
// flat computed inline from g_out + g_pq with hardware tanh (safe: 4096-term
// averaging kills the 5e-4 per-element error). Register-batched loads.
// Elected 64th block per batch does softmax / targets / importance / dist.
// ---------------------------------------------------------------------------
__global__ void __launch_bounds__(128) k2(
    const float* __restrict__ inputs, const float* __restrict__ mem_keys,
    const float* __restrict__ mem_vals,
    float* __restrict__ d_dist, float* __restrict__ d_imp)
{
    int m   = blockIdx.x;     // 0..63
    int b   = blockIdx.y;     // 0..3
    int tid = threadIdx.x;    // 0..127
    int wid = tid >> 5, lane = tid & 31;

    __shared__ float2 s_pq[TT];
    __shared__ float s_part[4];
    __shared__ float s_attn[MM];
    __shared__ float s_tgt2[2][FF];
    __shared__ float s_tgt[FF];
    __shared__ float s_red[4];
    __shared__ int   s_flag;

    if (tid < 64) s_pq[tid] = __ldcg(g_pq + b * TT + tid);

    // ---- batched loads: all 16 float4 in flight before any math ----
    const float4* go4 = (const float4*)(g_out + b * TF);
    const float4* kr4 = (const float4*)(mem_keys + m * TF);
    float4 a[8], kk[8];
#pragma unroll
    for (int j = 0; j < 8; j++) a[j]  = __ldcg(go4 + tid + j * 128);
#pragma unroll
    for (int j = 0; j < 8; j++) kk[j] = __ldg(kr4 + tid + j * 128);
    __syncthreads();   // s_pq ready

    float accd = 0.f;
#pragma unroll
    for (int j = 0; j < 8; j++) {
        int i4 = tid + j * 128;
        float2 pq = s_pq[i4 >> 4];
        float fx = tanh_fast((a[j].x >= 0.f) ? a[j].x * pq.x : a[j].x * pq.y);
        float fy = tanh_fast((a[j].y >= 0.f) ? a[j].y * pq.x : a[j].y * pq.y);
        float fz = tanh_fast((a[j].z >= 0.f) ? a[j].z * pq.x : a[j].z * pq.y);
        float fw = tanh_fast((a[j].w >= 0.f) ? a[j].w * pq.x : a[j].w * pq.y);
        accd = fmaf(fx, kk[j].x, accd);
        accd = fmaf(fy, kk[j].y, accd);
        accd = fmaf(fz, kk[j].z, accd);
        accd = fmaf(fw, kk[j].w, accd);
    }
    for (int o = 16; o; o >>= 1)
        accd += __shfl_xor_sync(0xffffffffu, accd, o);
    if (lane == 0) s_part[wid] = accd;
    __syncthreads();
    if (tid == 0)
        g_logit[b * MM + m] = s_part[0] + s_part[1] + s_part[2] + s_part[3];

    // ---------------- Election (losers exit) ----------------
    __threadfence();
    if (tid == 0) {
        int old = atomicAdd(&g_cnt2[b], 1);
        s_flag = (old == MM - 1);
    }
    __syncthreads();
    if (!s_flag) return;
    if (tid == 0) atomicExch(&g_cnt2[b], 0);   // reset for next replay

    // ---------------- softmax / targets / importance / dist ----------------
    float v = (tid < MM) ? __ldcg(g_logit + b * MM + tid) : -1e30f;

    float m1 = v;
    for (int o = 16; o; o >>= 1) m1 = fmaxf(m1, __shfl_xor_sync(0xffffffffu, m1, o));
    if (lane == 0 && wid < 2) s_red[wid] = m1;
    __syncthreads();
    float ml = fmaxf(s_red[0], s_red[1]);

    float e = (tid < MM) ? expf(v - ml) : 0.f;
    if (tid < MM) s_attn[tid] = e;
    float s1 = e;
    for (int o = 16; o; o >>= 1) s1 += __shfl_xor_sync(0xffffffffu, s1, o);
    if (lane == 0 && wid < 2) s_red[2 + wid] = s1;
    __syncthreads();
    float invsum = 1.f / (s_red[2] + s_red[3]);
    // importance = max(attn) = exp(0) * invsum = invsum

    // targets: 2-way split over m (threads 0-63: m 0..31, 64-127: m 32..63)
    {
        int f    = tid & 63;
        int half = tid >> 6;
        float accv = 0.f;
#pragma unroll 8
        for (int mm = 0; mm < 32; mm++) {
            int mr = half * 32 + mm;
            accv = fmaf(s_attn[mr], __ldg(mem_vals + mr * FF + f), accv);
        }
        s_tgt2[half][f] = accv;
    }
    __syncthreads();
    if (tid < FF) s_tgt[tid] = (s_tgt2[0][tid] + s_tgt2[1][tid]) * invsum;
    __syncthreads();

    // dist[t] = 0.5 - hard_sigmoid(||inputs[b,t,:] - targets||)
    if (tid < TT) {
        const float4* ir4 = (const float4*)(inputs + (b * TT + tid) * FF);
        const float4* tg4 = (const float4*)s_tgt;
        float4 xr[16];
#pragma unroll
        for (int j = 0; j < 16; j++) xr[j] = __ldg(ir4 + j);
        float accn = 0.f;
#pragma unroll
        for (int j = 0; j < 16; j++) {
            float4 tg = tg4[j];
            float dx = xr[j].x - tg.x, dy = xr[j].y - tg.y;
            float dz = xr[j].z - tg.z, dw = xr[j].w - tg.w;
            accn = fmaf(dx, dx, accn);
            accn = fmaf(dy, dy, accn);
            accn = fmaf(dz, dz, accn);
            accn = fmaf(dw, dw, accn);
        }
        float nrm = sqrtf(accn);
        float hs  = fminf(fmaxf(0.2f * nrm + 0.5f, 0.f), 1.f);
        d_dist[b * TT + tid] = 0.5f - hs;
        d_imp [b * TT + tid] = invsum;
    }
}

// ---------------------------------------------------------------------------
// Output layout: dist [B*T] | importances [B*T] | output [B*T*F]
// ---------------------------------------------------------------------------
extern "C" void kernel_launch(void* const* d_in, const int* in_sizes, int n_in,
                              void* d_out, int out_size)
{
    const float* inputs   = (const float*)d_in[0];
    const float* Wk       = (const float*)d_in[1];
    const float* bk       = (const float*)d_in[2];
    const float* Wv       = (const float*)d_in[3];
    const float* bv       = (const float*)d_in[4];
    const float* ws       = (const float*)d_in[5];
    const float* mem_keys = (const float*)d_in[6];
    const float* mem_vals = (const float*)d_in[7];

    float* out       = (float*)d_out;
    float* d_dist    = out;                 // B*T
    float* d_imp     = out + BB * TT;       // B*T
    float* out_final = out + 2 * BB * TT;   // B*T*F

    dim3 g1(16, BB);
    k1<<<g1, 256>>>(inputs, Wk, bk, Wv, bv, ws, out_final);
    dim3 g2(MM, BB);
    k2<<<g2, 128>>>(inputs, mem_keys, mem_vals, d_dist, d_imp);
}

// round 11
// speedup vs baseline: 2.4250x; 1.1067x over previous
#include <cuda_runtime.h>
#include <math.h>

#define BB 4
#define TT 64
#define FF 64
#define UU 64
#define MM 64
#define TF 4096   // T*F

// Scratch (device globals: no allocation allowed)
__device__ float  g_h[BB * TT * UU];
__device__ float  g_out[BB * TT * FF];
__device__ float  g_score[BB * TT * FF];
__device__ float2 g_pq[BB * TT];       // (pqmax, pqmin) per (b,t)
__device__ float  g_logit[BB * MM];    // zeroed by k1 elected each launch
__device__ int    g_cnt1[BB];          // zero-init; elected resets each launch
__device__ int    g_cnt2[BB];

// Hardware tanh (sm_75+): ~2^-11 rel error. Used only for score (argmax
// comparisons) and flat (4096-term averaged dot) — never for `output`.
__device__ __forceinline__ float tanh_fast(float x) {
    float y;
    asm("tanh.approx.f32 %0, %1;" : "=f"(y) : "f"(x));
    return y;
}

// ---------------------------------------------------------------------------
// K1: grid (32, BB), 128 threads. Block handles 2 timesteps of batch b
// (spreads the ~1M-MUFU score computation over 128 SMs).
// Election: 32nd-arriving block per batch does phase B: zero g_logit,
// argmax paths, selected sets, extremes -> g_pq. Losers exit.
// ---------------------------------------------------------------------------
__global__ void __launch_bounds__(128) k1(
    const float* __restrict__ inputs, const float* __restrict__ Wk,
    const float* __restrict__ bk,     const float* __restrict__ Wv,
    const float* __restrict__ bv,     const float* __restrict__ ws,
    float* __restrict__ out_final)
{
    int b   = blockIdx.y;
    int tid = threadIdx.x;          // 0..127
    int lt  = tid >> 6;             // local t 0..1
    int f   = tid & 63;
    int t   = (blockIdx.x << 1) + lt;
    int bt  = b * TT + t;
    int wid = tid >> 5, lane = tid & 31;

    __shared__ float s_in[2][FF], s_h[2][FF];
    __shared__ float s_score[TF];           // 16 KB (elected only)
    __shared__ int   s_idxt[TT], s_idxf[FF];
    __shared__ int   s_usel[UU], s_ssel[TT];
    __shared__ float2 s_qred[4];
    __shared__ float s_q[2];
    __shared__ int   s_flag;

    // ---------------- Phase A ----------------
    s_in[lt][f] = inputs[bt * FF + f];
    __syncthreads();

    float acc = bk[f];
#pragma unroll 16
    for (int k = 0; k < FF; k++)
        acc = fmaf(s_in[lt][k], Wk[k * UU + f], acc);
    float hv = tanhf(acc);          // accurate: h feeds checked `output`
    s_h[lt][f] = hv;
    g_h[bt * UU + f] = hv;
    __syncthreads();

    float acc2 = bv[f];
#pragma unroll 16
    for (int u = 0; u < UU; u++)
        acc2 = fmaf(s_h[lt][u], Wv[u * FF + f], acc2);
    g_out[bt * FF + f]     = acc2;
    out_final[bt * FF + f] = acc2;

    // score: feeds argmax only -> hardware tanh
    float c  = acc2 * __ldg(ws + 63);
    float sc = 0.f;
#pragma unroll 16
    for (int u = 0; u < UU; u++)
        sc += tanh_fast(s_h[lt][u] * c);
    g_score[bt * FF + f] = sc;

    // ---------------- Election (losers exit) ----------------
    __threadfence();
    if (tid == 0) {
        int old = atomicAdd(&g_cnt1[b], 1);
        s_flag = (old == 31);
    }
    __syncthreads();
    if (!s_flag) return;
    if (tid == 0) atomicExch(&g_cnt1[b], 0);   // reset for next replay

    // ---------------- Phase B (elected block, 128 threads) ----------------
    // Zero this batch's logit accumulators for K2 (kernel-boundary ordered)
    if (tid < 64) g_logit[b * MM + tid] = 0.f;

    // Stage score matrix (siblings wrote it -> L2), explicit MLP=8
    {
        const float4* gs4 = (const float4*)(g_score + b * TF);
        float4* ss4 = (float4*)s_score;
        float4 r[8];
#pragma unroll
        for (int j = 0; j < 8; j++) r[j] = __ldcg(gs4 + tid + j * 128);
#pragma unroll
        for (int j = 0; j < 8; j++) ss4[tid + j * 128] = r[j];
    }
    if (tid < 64) { s_usel[tid] = 0; s_ssel[tid] = 0; }
    __syncthreads();

    // idx_f[f] = first argmax_t (column scan) — threads 0..63
    // idx_t[t] = first argmax_f (rotated row scan + smallest-index tie-break)
    if (tid < 64) {
        int ff = tid;
        float best = s_score[ff]; int bi = 0;
#pragma unroll 8
        for (int t2 = 1; t2 < TT; t2++) {
            float v = s_score[t2 * FF + ff];
            if (v > best) { best = v; bi = t2; }
        }
        s_idxf[ff] = bi;
    } else {
        int tt2 = tid - 64;
        float best = -1e30f; int bi = FF;
#pragma unroll 8
        for (int k = 0; k < FF; k++) {
            int ff = (tt2 + k) & 63;
            float v = s_score[tt2 * FF + ff];
            if (v > best || (v == best && ff < bi)) { best = v; bi = ff; }
        }
        s_idxt[tt2] = bi;
    }
    __syncthreads();

    if (tid < 64) { s_usel[s_idxt[tid]] = 1; s_ssel[s_idxf[tid]] = 1; }
    __syncthreads();

    // q extremes over selected s — shfl reduction across 4 warps
    {
        bool  on = (tid < 64) && s_ssel[tid];
        float w  = on ? __ldg(ws + tid) : 0.f;
        float qmx = on ? w : -1e30f;
        float qmn = on ? w :  1e30f;
        for (int o = 16; o; o >>= 1) {
            qmx = fmaxf(qmx, __shfl_xor_sync(0xffffffffu, qmx, o));
            qmn = fminf(qmn, __shfl_xor_sync(0xffffffffu, qmn, o));
        }
        if (lane == 0) s_qred[wid] = make_float2(qmx, qmn);
    }
    __syncthreads();
    if (tid == 0) {
        float qmx = -1e30f, qmn = 1e30f;
#pragma unroll
        for (int w2 = 0; w2 < 4; w2++) {
            qmx = fmaxf(qmx, s_qred[w2].x);
            qmn = fminf(qmn, s_qred[w2].y);
        }
        s_q[0] = qmx; s_q[1] = qmn;
    }

    // h extremes per t over selected u (threads 0..63, one t each)
    float hmax = -1e30f, hmin = 1e30f;
    if (tid < 64) {
        const float* hr = g_h + (b * TT + tid) * UU;
#pragma unroll 8
        for (int u = 0; u < UU; u++) {
            float h = __ldcg(hr + u);
            if (s_usel[u]) { hmax = fmaxf(hmax, h); hmin = fminf(hmin, h); }
        }
    }
    __syncthreads();

    if (tid < 64) {
        float qmax = s_q[0], qmin = s_q[1];
        float p1 = hmax * qmax, p2 = hmax * qmin, p3 = hmin * qmax, p4 = hmin * qmin;
        float pqmax = fmaxf(fmaxf(p1, p2), fmaxf(p3, p4));
        float pqmin = fminf(fminf(p1, p2), fminf(p3, p4));
        g_pq[b * TT + tid] = make_float2(pqmax, pqmin);
    }
}

// ---------------------------------------------------------------------------
// K2: grid (16, BB), 256 threads. Block (chunk, b):
//   1. compute flat[chunk] (256 elems) ONCE into smem (256 tanh)
//   2. warp w: dot chunk against keys m = w*8..w*8+7, atomicAdd partial logits
//   3. elected 16th block per batch: softmax / targets / importance / dist
// ---------------------------------------------------------------------------
__global__ void __launch_bounds__(256) k2(
    const float* __restrict__ inputs, const float* __restrict__ mem_keys,
    const float* __restrict__ mem_vals,
    float* __restrict__ d_dist, float* __restrict__ d_imp)
{
    int chunk = blockIdx.x;    // 0..15
    int b     = blockIdx.y;    // 0..3
    int tid   = threadIdx.x;   // 0..255
    int wid   = tid >> 5, lane = tid & 31;
    int base  = chunk * 256;

    __shared__ float s_flat[256];
    __shared__ float s_attn[MM];
    __shared__ float s_tgt4[4][FF];
    __shared__ float s_tgt[FF];
    __shared__ float s_red[4];
    __shared__ int   s_flag;

    // ---- 1. flat chunk (one tanh per element, no redundancy) ----
    {
        int i = base + tid;
        float2 pq = g_pq[b * TT + (i >> 6)];
        float x = __ldcg(g_out + b * TF + i);
        s_flat[tid] = tanh_fast((x >= 0.f) ? x * pq.x : x * pq.y);
    }
    __syncthreads();

    // ---- 2. per-warp dot against 8 keys ----
    {
        // flat slice for this lane: 8 consecutive floats
        const float4* fl4 = (const float4*)(s_flat + lane * 8);
        float4 f0 = fl4[0], f1 = fl4[1];

        float sums[8];
#pragma unroll
        for (int mi = 0; mi < 8; mi++) {
            int m = wid * 8 + mi;
            const float4* kp = (const float4*)(mem_keys + m * TF + base + lane * 8);
            float4 k0 = __ldg(kp);
            float4 k1 = __ldg(kp + 1);
            float s = 0.f;
            s = fmaf(f0.x, k0.x, s); s = fmaf(f0.y, k0.y, s);
            s = fmaf(f0.z, k0.z, s); s = fmaf(f0.w, k0.w, s);
            s = fmaf(f1.x, k1.x, s); s = fmaf(f1.y, k1.y, s);
            s = fmaf(f1.z, k1.z, s); s = fmaf(f1.w, k1.w, s);
            for (int o = 16; o; o >>= 1)
                s += __shfl_xor_sync(0xffffffffu, s, o);
            sums[mi] = s;
        }
        if (lane == 0) {
#pragma unroll
            for (int mi = 0; mi < 8; mi++)
                atomicAdd(&g_logit[b * MM + wid * 8 + mi], sums[mi]);
        }
    }

    // ---------------- Election (losers exit) ----------------
    __threadfence();
    if (tid == 0) {
        int old = atomicAdd(&g_cnt2[b], 1);
        s_flag = (old == 15);
    }
    __syncthreads();
    if (!s_flag) return;
    if (tid == 0) atomicExch(&g_cnt2[b], 0);   // reset for next replay

    // ---------------- 3. softmax / targets / importance / dist ----------------
    float v = (tid < MM) ? __ldcg(g_logit + b * MM + tid) : -1e30f;

    float m1 = v;
    for (int o = 16; o; o >>= 1) m1 = fmaxf(m1, __shfl_xor_sync(0xffffffffu, m1, o));
    if (lane == 0 && wid < 2) s_red[wid] = m1;
    __syncthreads();
    float ml = fmaxf(s_red[0], s_red[1]);

    float e = (tid < MM) ? expf(v - ml) : 0.f;
    if (tid < MM) s_attn[tid] = e;
    float s1 = e;
    for (int o = 16; o; o >>= 1) s1 += __shfl_xor_sync(0xffffffffu, s1, o);
    if (lane == 0 && wid < 2) s_red[2 + wid] = s1;
    __syncthreads();
    float invsum = 1.f / (s_red[2] + s_red[3]);
    // importance = max(attn) = exp(0) * invsum = invsum

    // targets: 4-way split over m (quarter q handles m = q*16..q*16+15)
    {
        int f = tid & 63;
        int q = tid >> 6;
        float accv = 0.f;
#pragma unroll
        for (int mm = 0; mm < 16; mm++) {
            int mr = q * 16 + mm;
            accv = fmaf(s_attn[mr], __ldg(mem_vals + mr * FF + f), accv);
        }
        s_tgt4[q][f] = accv;
    }
    __syncthreads();
    if (tid < FF)
        s_tgt[tid] = (s_tgt4[0][tid] + s_tgt4[1][tid] +
                      s_tgt4[2][tid] + s_tgt4[3][tid]) * invsum;
    __syncthreads();

    // dist[t] = 0.5 - hard_sigmoid(||inputs[b,t,:] - targets||)
    if (tid < TT) {
        const float4* ir4 = (const float4*)(inputs + (b * TT + tid) * FF);
        const float4* tg4 = (const float4*)s_tgt;
        float4 xr[16];
#pragma unroll
        for (int j = 0; j < 16; j++) xr[j] = __ldg(ir4 + j);
        float accn = 0.f;
#pragma unroll
        for (int j = 0; j < 16; j++) {
            float4 tg = tg4[j];
            float dx = xr[j].x - tg.x, dy = xr[j].y - tg.y;
            float dz = xr[j].z - tg.z, dw = xr[j].w - tg.w;
            accn = fmaf(dx, dx, accn);
            accn = fmaf(dy, dy, accn);
            accn = fmaf(dz, dz, accn);
            accn = fmaf(dw, dw, accn);
        }
        float nrm = sqrtf(accn);
        float hs  = fminf(fmaxf(0.2f * nrm + 0.5f, 0.f), 1.f);
        d_dist[b * TT + tid] = 0.5f - hs;
        d_imp [b * TT + tid] = invsum;
    }
}

// ---------------------------------------------------------------------------
// Output layout: dist [B*T] | importances [B*T] | output [B*T*F]
// ---------------------------------------------------------------------------
extern "C" void kernel_launch(void* const* d_in, const int* in_sizes, int n_in,
                              void* d_out, int out_size)
{
    const float* inputs   = (const float*)d_in[0];
    const float* Wk       = (const float*)d_in[1];
    const float* bk       = (const float*)d_in[2];
    const float* Wv       = (const float*)d_in[3];
    const float* bv       = (const float*)d_in[4];
    const float* ws       = (const float*)d_in[5];
    const float* mem_keys = (const float*)d_in[6];
    const float* mem_vals = (const float*)d_in[7];

    float* out       = (float*)d_out;
    float* d_dist    = out;                 // B*T
    float* d_imp     = out + BB * TT;       // B*T
    float* out_final = out + 2 * BB * TT;   // B*T*F

    dim3 g1(32, BB);
    k1<<<g1, 128>>>(inputs, Wk, bk, Wv, bv, ws, out_final);
    dim3 g2(16, BB);
    k2<<<g2, 256>>>(inputs, mem_keys, mem_vals, d_dist, d_imp);
}